// round 7
// baseline (speedup 1.0000x reference)
#include <cuda_runtime.h>
#include <math.h>
#include <string.h>

#define BATCH  64
#define TSTEPS 512
#define DIN    512
#define DH     1024

typedef unsigned long long ull;

// ---------------- small helpers ----------------
__device__ __forceinline__ ull pack2(float v) {
    ull r; asm("mov.b64 %0, {%1, %1};" : "=l"(r) : "f"(v)); return r;
}
__device__ __forceinline__ ull f2u(float2 v) { ull r; memcpy(&r, &v, 8); return r; }
__device__ __forceinline__ float2 u2f(ull v) { float2 r; memcpy(&r, &v, 8); return r; }
__device__ __forceinline__ void fma2(ull& acc, ull a, ull b) {
    asm("fma.rn.f32x2 %0, %1, %2, %0;" : "+l"(acc) : "l"(a), "l"(b));
}
__device__ __forceinline__ ull ld_acq(const ull* p) {
    ull v;
    asm volatile("ld.acquire.gpu.global.u64 %0, [%1];" : "=l"(v) : "l"(p) : "memory");
    return v;
}
__device__ __forceinline__ void red_rel_add(ull* p, ull v) {
    asm volatile("red.release.gpu.global.add.u64 [%0], %1;" :: "l"(p), "l"(v) : "memory");
}

// ---------------- dataflow flags (monotonic, replay-safe) ----------------
// g_flags[gm][c]: total completed (producer-block, step) increments for
// 64-column chunk c of batch-group gm. 4 producers per chunk per step.
__device__ ull g_flags[2][16];

// ---------------- Kernel A: C = x @ W + bias  (128x128 tile, f32x2) --------
__global__ __launch_bounds__(256) void gemm_xw_kernel(
    const float* __restrict__ X, const float* __restrict__ W,
    const float* __restrict__ bias, float* __restrict__ C)
{
    __shared__ float As[16][132];
    __shared__ float Bs[16][132];

    const int tid   = threadIdx.x;
    const int tx    = tid & 15;
    const int ty    = tid >> 4;
    const int mBase = blockIdx.y << 7;
    const int nBase = blockIdx.x << 7;

    ull acc[4][8];
#pragma unroll
    for (int p = 0; p < 4; ++p)
#pragma unroll
        for (int n = 0; n < 8; ++n) acc[p][n] = 0ull;

    for (int k0 = 0; k0 < DIN; k0 += 16) {
#pragma unroll
        for (int p = 0; p < 2; ++p) {
            int idx = tid + p * 256;
            int m = idx >> 2, kq = (idx & 3) << 2;
            float4 v = *(const float4*)(X + (size_t)(mBase + m) * DIN + k0 + kq);
            As[kq + 0][m] = v.x;
            As[kq + 1][m] = v.y;
            As[kq + 2][m] = v.z;
            As[kq + 3][m] = v.w;
        }
#pragma unroll
        for (int p = 0; p < 2; ++p) {
            int idx = tid + p * 256;
            int k = idx >> 5, nq = (idx & 31) << 2;
            *(float4*)&Bs[k][nq] = *(const float4*)(W + (size_t)(k0 + k) * DH + nBase + nq);
        }
        __syncthreads();
#pragma unroll
        for (int kk = 0; kk < 16; ++kk) {
            float4 a0 = *(const float4*)&As[kk][ty * 8];
            float4 a1 = *(const float4*)&As[kk][ty * 8 + 4];
            float4 b0 = *(const float4*)&Bs[kk][tx * 8];
            float4 b1 = *(const float4*)&Bs[kk][tx * 8 + 4];
            ull am[4];
            am[0] = f2u(make_float2(a0.x, a0.y));
            am[1] = f2u(make_float2(a0.z, a0.w));
            am[2] = f2u(make_float2(a1.x, a1.y));
            am[3] = f2u(make_float2(a1.z, a1.w));
            ull bn[8];
            bn[0] = pack2(b0.x); bn[1] = pack2(b0.y); bn[2] = pack2(b0.z); bn[3] = pack2(b0.w);
            bn[4] = pack2(b1.x); bn[5] = pack2(b1.y); bn[6] = pack2(b1.z); bn[7] = pack2(b1.w);
#pragma unroll
            for (int p = 0; p < 4; ++p)
#pragma unroll
                for (int n = 0; n < 8; ++n)
                    fma2(acc[p][n], am[p], bn[n]);
        }
        __syncthreads();
    }

    float4 bb0 = *(const float4*)(bias + nBase + tx * 8);
    float4 bb1 = *(const float4*)(bias + nBase + tx * 8 + 4);
    float bbs[8] = {bb0.x, bb0.y, bb0.z, bb0.w, bb1.x, bb1.y, bb1.z, bb1.w};

#pragma unroll
    for (int p = 0; p < 4; ++p) {
        float2 c[8];
#pragma unroll
        for (int n = 0; n < 8; ++n) c[n] = u2f(acc[p][n]);
        int row0 = mBase + ty * 8 + p * 2;
        float* out0 = C + (size_t)row0 * DH + nBase + tx * 8;
        float* out1 = out0 + DH;
        float4 o;
        o.x = c[0].x + bbs[0]; o.y = c[1].x + bbs[1]; o.z = c[2].x + bbs[2]; o.w = c[3].x + bbs[3];
        *(float4*)out0 = o;
        o.x = c[4].x + bbs[4]; o.y = c[5].x + bbs[5]; o.z = c[6].x + bbs[6]; o.w = c[7].x + bbs[7];
        *(float4*)(out0 + 4) = o;
        o.x = c[0].y + bbs[0]; o.y = c[1].y + bbs[1]; o.z = c[2].y + bbs[2]; o.w = c[3].y + bbs[3];
        *(float4*)out1 = o;
        o.x = c[4].y + bbs[4]; o.y = c[5].y + bbs[5]; o.z = c[6].y + bbs[6]; o.w = c[7].y + bbs[7];
        *(float4*)(out1 + 4) = o;
    }
}

// ---------------- Kernel B: persistent recurrence, dataflow flags ----------
// 128 blocks: gm = bid>>6 (m-tile 32), gn = bid&63 (j-tile 16). 16 warps.
// Warp w owns k-range [64w, 64w+64) and waits ONLY on flag[gm][w]
// (its 4 producer blocks gn = 4w..4w+3). No grid barrier.
// Flag poll: LANE 0 ONLY (avoids 512-thread LSU/L2 poll storm), then
// __syncwarp (bar.warp.sync: memory-ordering among warp lanes).
// h staged per warp: coalesced __ldcg + STS. R persistent in smem [j][k].
// f32x2 broadcast micro-tile 4x4. Partials alias H.
#define TPB 512
#define HSTRIDE 1028
#define H_OFF 0
#define R_OFF (32 * HSTRIDE)
#define P_OFF 0
#define SMEM_FLOATS (R_OFF + 16 * HSTRIDE)   // 49344 floats = 197376 B

__global__ __launch_bounds__(TPB, 1)
void rnn_recur_kernel(const float* __restrict__ h0, const float* __restrict__ R, float* out)
{
    extern __shared__ float S[];
    __shared__ ull base_s;

    const int tid    = threadIdx.x;
    const int w      = tid >> 5;
    const int lane   = tid & 31;
    const int m_lane = lane & 7;
    const int j_lane = lane >> 3;
    const int gm     = (int)(blockIdx.x >> 6);
    const int gn     = (int)(blockIdx.x & 63);
    const int mBase  = gm << 5;
    const int jBase  = gn << 4;

    // ---- stage R transposed into smem [j][k] (once) ----
#pragma unroll
    for (int p = 0; p < 8; ++p) {
        int idx = tid + p * TPB;
        int k = idx >> 2, q = idx & 3;
        float4 v = *(const float4*)(R + (size_t)k * DH + jBase + q * 4);
        S[R_OFF + (q * 4 + 0) * HSTRIDE + k] = v.x;
        S[R_OFF + (q * 4 + 1) * HSTRIDE + k] = v.y;
        S[R_OFF + (q * 4 + 2) * HSTRIDE + k] = v.z;
        S[R_OFF + (q * 4 + 3) * HSTRIDE + k] = v.w;
    }
    // snapshot monotonic flag base (all flags equal at kernel entry)
    if (tid == 0) base_s = ld_acq(&g_flags[gm][0]);
    __syncthreads();
    const ull base = base_s;

    const float* Hp = S + H_OFF + (size_t)m_lane * HSTRIDE + w * 64;
    const float* Rp = S + R_OFF + (size_t)j_lane * HSTRIDE + w * 64;
    const int m_l = tid >> 4, j_l = tid & 15;       // epilogue decode
    const ull* myflag  = &g_flags[gm][w];
    ull* prodflag      = &g_flags[gm][gn >> 2];

    // h staging decode: lanes 0-15 row 2p, lanes 16-31 row 2p+1
    const int kf    = w * 64 + (lane & 15) * 4;
    const int rhalf = lane >> 4;

#pragma unroll 1
    for (int t = 0; t < TSTEPS; ++t) {
        // ---- prefetch this block's preact (only this block touches it) ----
        const size_t oi = ((size_t)(mBase + m_l) * TSTEPS + t) * DH + jBase + j_l;
        const float pre = __ldcg(out + oi);

        // ---- wait for my chunk's 4 producers (lane 0 only, then syncwarp) ----
        if (t > 0) {
            if (lane == 0) {
                const ull target = base + 4ull * (ull)t;
                while (ld_acq(myflag) < target) { }
            }
            __syncwarp();
        }

        // ---- stage h slice: 32 rows x my 64 k (coalesced, L1-bypassing) ----
        {
            const float* hb;
            size_t rstr;
            if (t == 0) { hb = h0 + (size_t)mBase * DH; rstr = DH; }
            else {
                hb = out + (size_t)(t - 1) * DH + (size_t)mBase * ((size_t)TSTEPS * DH);
                rstr = (size_t)TSTEPS * DH;
            }
#pragma unroll
            for (int p = 0; p < 16; ++p) {
                const int row = p * 2 + rhalf;
                float4 v = __ldcg((const float4*)(hb + (size_t)row * rstr + kf));
                *(float4*)&S[H_OFF + row * HSTRIDE + kf] = v;
            }
        }
        __syncwarp();

        // ---- compute: 4x4 micro-tile, f32x2 pairs over k ----
        ull acc[4][4];
#pragma unroll
        for (int mi = 0; mi < 4; ++mi)
#pragma unroll
            for (int ji = 0; ji < 4; ++ji) acc[mi][ji] = 0ull;

#pragma unroll 4
        for (int it = 0; it < 16; ++it) {
            const int off = it * 4;
            float4 h[4], r[4];
#pragma unroll
            for (int mi = 0; mi < 4; ++mi)
                h[mi] = *(const float4*)(Hp + (size_t)(mi * 8) * HSTRIDE + off);
#pragma unroll
            for (int ji = 0; ji < 4; ++ji)
                r[ji] = *(const float4*)(Rp + (size_t)(ji * 4) * HSTRIDE + off);
#pragma unroll
            for (int mi = 0; mi < 4; ++mi) {
                ull hlo = f2u(make_float2(h[mi].x, h[mi].y));
                ull hhi = f2u(make_float2(h[mi].z, h[mi].w));
#pragma unroll
                for (int ji = 0; ji < 4; ++ji) {
                    fma2(acc[mi][ji], hlo, f2u(make_float2(r[ji].x, r[ji].y)));
                    fma2(acc[mi][ji], hhi, f2u(make_float2(r[ji].z, r[ji].w)));
                }
            }
        }

        __syncthreads();   // (1) all H reads done before P overwrites

        // ---- partials to smem (P aliases H) ----
#pragma unroll
        for (int mi = 0; mi < 4; ++mi)
#pragma unroll
            for (int ji = 0; ji < 4; ++ji) {
                float2 c = u2f(acc[mi][ji]);
                int m_loc = m_lane + 8 * mi;
                int j_loc = j_lane + 4 * ji;
                S[P_OFF + (m_loc * 16 + j_loc) * 17 + w] = c.x + c.y;
            }
        __syncthreads();   // (2) partials visible

        // ---- reduce 16 partials + preact + tanh + store h_t ----
        {
            const float* row = S + P_OFF + tid * 17;
            float s0 = 0.f, s1 = 0.f;
#pragma unroll
            for (int q = 0; q < 8; ++q) { s0 += row[q]; s1 += row[q + 8]; }
            out[oi] = tanhf(pre + s0 + s1);
        }

        __syncthreads();   // (3) STGs + P reads done before flag / H restage

        // ---- announce: this block finished step t (release) ----
        if (tid == 0) red_rel_add(prodflag, 1ull);
    }
}

// ---------------- launch ----------------
extern "C" void kernel_launch(void* const* d_in, const int* in_sizes, int n_in,
                              void* d_out, int out_size)
{
    const float* x  = (const float*)d_in[0];   // [64,512,512]
    const float* h0 = (const float*)d_in[1];   // [64,1024]
    const float* W  = (const float*)d_in[2];   // [512,1024]
    const float* R  = (const float*)d_in[3];   // [1024,1024]
    const float* b  = (const float*)d_in[4];   // [1,1024]
    float* out = (float*)d_out;                // [64,512,1024]

    const int smem_bytes = SMEM_FLOATS * 4;
    cudaFuncSetAttribute(rnn_recur_kernel,
                         cudaFuncAttributeMaxDynamicSharedMemorySize, smem_bytes);

    dim3 gridA(DH / 128, (BATCH * TSTEPS) / 128);  // (8, 256)
    gemm_xw_kernel<<<gridA, 256>>>(x, W, b, out);

    rnn_recur_kernel<<<128, TPB, smem_bytes>>>(h0, R, out);
}

// round 8
// speedup vs baseline: 1.4197x; 1.4197x over previous
#include <cuda_runtime.h>
#include <math.h>
#include <string.h>

#define BATCH  64
#define TSTEPS 512
#define DIN    512
#define DH     1024

typedef unsigned long long ull;

// ---------------- small helpers ----------------
__device__ __forceinline__ ull pack2(float v) {
    ull r; asm("mov.b64 %0, {%1, %1};" : "=l"(r) : "f"(v)); return r;
}
__device__ __forceinline__ ull f2u(float2 v) { ull r; memcpy(&r, &v, 8); return r; }
__device__ __forceinline__ float2 u2f(ull v) { float2 r; memcpy(&r, &v, 8); return r; }
__device__ __forceinline__ void fma2(ull& acc, ull a, ull b) {
    asm("fma.rn.f32x2 %0, %1, %2, %0;" : "+l"(acc) : "l"(a), "l"(b));
}
__device__ __forceinline__ ull ld_acq(const ull* p) {
    ull v;
    asm volatile("ld.acquire.gpu.global.u64 %0, [%1];" : "=l"(v) : "l"(p) : "memory");
    return v;
}
__device__ __forceinline__ void red_rel_add(ull* p, ull v) {
    asm volatile("red.release.gpu.global.add.u64 [%0], %1;" :: "l"(p), "l"(v) : "memory");
}
__device__ __forceinline__ unsigned s2u(const void* p) {
    unsigned a;
    asm("{ .reg .u64 t; cvta.to.shared.u64 t, %1; cvt.u32.u64 %0, t; }" : "=r"(a) : "l"(p));
    return a;
}
__device__ __forceinline__ void cp_async16(unsigned dst, const void* src) {
    asm volatile("cp.async.cg.shared.global [%0], [%1], 16;" :: "r"(dst), "l"(src) : "memory");
}
__device__ __forceinline__ void cp_async_wait_all() {
    asm volatile("cp.async.commit_group;\n\tcp.async.wait_group 0;" ::: "memory");
}

// ---------------- dataflow flags (monotonic, replay-safe) ----------------
// g_flags[gm][c]: completed (producer-block, step) increments for 64-col
// chunk c of batch-group gm. 4 producers per chunk per step.
__device__ ull g_flags[2][16];

// ---------------- Kernel A: C = x @ W + bias  (128x128 tile, f32x2) --------
__global__ __launch_bounds__(256) void gemm_xw_kernel(
    const float* __restrict__ X, const float* __restrict__ W,
    const float* __restrict__ bias, float* __restrict__ C)
{
    __shared__ float As[16][132];
    __shared__ float Bs[16][132];

    const int tid   = threadIdx.x;
    const int tx    = tid & 15;
    const int ty    = tid >> 4;
    const int mBase = blockIdx.y << 7;
    const int nBase = blockIdx.x << 7;

    ull acc[4][8];
#pragma unroll
    for (int p = 0; p < 4; ++p)
#pragma unroll
        for (int n = 0; n < 8; ++n) acc[p][n] = 0ull;

    for (int k0 = 0; k0 < DIN; k0 += 16) {
#pragma unroll
        for (int p = 0; p < 2; ++p) {
            int idx = tid + p * 256;
            int m = idx >> 2, kq = (idx & 3) << 2;
            float4 v = *(const float4*)(X + (size_t)(mBase + m) * DIN + k0 + kq);
            As[kq + 0][m] = v.x;
            As[kq + 1][m] = v.y;
            As[kq + 2][m] = v.z;
            As[kq + 3][m] = v.w;
        }
#pragma unroll
        for (int p = 0; p < 2; ++p) {
            int idx = tid + p * 256;
            int k = idx >> 5, nq = (idx & 31) << 2;
            *(float4*)&Bs[k][nq] = *(const float4*)(W + (size_t)(k0 + k) * DH + nBase + nq);
        }
        __syncthreads();
#pragma unroll
        for (int kk = 0; kk < 16; ++kk) {
            float4 a0 = *(const float4*)&As[kk][ty * 8];
            float4 a1 = *(const float4*)&As[kk][ty * 8 + 4];
            float4 b0 = *(const float4*)&Bs[kk][tx * 8];
            float4 b1 = *(const float4*)&Bs[kk][tx * 8 + 4];
            ull am[4];
            am[0] = f2u(make_float2(a0.x, a0.y));
            am[1] = f2u(make_float2(a0.z, a0.w));
            am[2] = f2u(make_float2(a1.x, a1.y));
            am[3] = f2u(make_float2(a1.z, a1.w));
            ull bn[8];
            bn[0] = pack2(b0.x); bn[1] = pack2(b0.y); bn[2] = pack2(b0.z); bn[3] = pack2(b0.w);
            bn[4] = pack2(b1.x); bn[5] = pack2(b1.y); bn[6] = pack2(b1.z); bn[7] = pack2(b1.w);
#pragma unroll
            for (int p = 0; p < 4; ++p)
#pragma unroll
                for (int n = 0; n < 8; ++n)
                    fma2(acc[p][n], am[p], bn[n]);
        }
        __syncthreads();
    }

    float4 bb0 = *(const float4*)(bias + nBase + tx * 8);
    float4 bb1 = *(const float4*)(bias + nBase + tx * 8 + 4);
    float bbs[8] = {bb0.x, bb0.y, bb0.z, bb0.w, bb1.x, bb1.y, bb1.z, bb1.w};

#pragma unroll
    for (int p = 0; p < 4; ++p) {
        float2 c[8];
#pragma unroll
        for (int n = 0; n < 8; ++n) c[n] = u2f(acc[p][n]);
        int row0 = mBase + ty * 8 + p * 2;
        float* out0 = C + (size_t)row0 * DH + nBase + tx * 8;
        float* out1 = out0 + DH;
        float4 o;
        o.x = c[0].x + bbs[0]; o.y = c[1].x + bbs[1]; o.z = c[2].x + bbs[2]; o.w = c[3].x + bbs[3];
        *(float4*)out0 = o;
        o.x = c[4].x + bbs[4]; o.y = c[5].x + bbs[5]; o.z = c[6].x + bbs[6]; o.w = c[7].x + bbs[7];
        *(float4*)(out0 + 4) = o;
        o.x = c[0].y + bbs[0]; o.y = c[1].y + bbs[1]; o.z = c[2].y + bbs[2]; o.w = c[3].y + bbs[3];
        *(float4*)out1 = o;
        o.x = c[4].y + bbs[4]; o.y = c[5].y + bbs[5]; o.z = c[6].y + bbs[6]; o.w = c[7].y + bbs[7];
        *(float4*)(out1 + 4) = o;
    }
}

// ---------------- Kernel B: persistent recurrence, dataflow flags ----------
// 128 blocks: gm = bid>>6 (m-tile 32), gn = bid&63 (j-tile 16). 16 warps.
// Warp w owns k-range [64w,+64), waits only on flag[gm][w] (producers
// gn = 4w..4w+3). h staged per warp via cp.async.cg (L2->smem direct,
// warp-local wait_group). R persistent in smem [j][k]. f32x2 broadcast
// micro-tile 4x4. P is a SEPARATE region (no alias) -> 2 syncthreads/step.
#define TPB 512
#define HSTRIDE 1028
#define H_OFF 0
#define R_OFF (32 * HSTRIDE)                  // 32896
#define P_OFF (R_OFF + 16 * HSTRIDE)          // 49344
#define SMEM_FLOATS (P_OFF + 512 * 17)        // 58048 floats = 232192 B

__global__ __launch_bounds__(TPB, 1)
void rnn_recur_kernel(const float* __restrict__ h0, const float* __restrict__ R, float* out)
{
    extern __shared__ float S[];

    const int tid    = threadIdx.x;
    const int w      = tid >> 5;
    const int lane   = tid & 31;
    const int m_lane = lane & 7;
    const int j_lane = lane >> 3;
    const int gm     = (int)(blockIdx.x >> 6);
    const int gn     = (int)(blockIdx.x & 63);
    const int mBase  = gm << 5;
    const int jBase  = gn << 4;

    const ull* myflag = &g_flags[gm][w];
    ull* prodflag     = &g_flags[gm][gn >> 2];

    // snapshot monotonic flag base (bounded launch-skew race is benign:
    // producers can be at most 1 step ahead at our first read)
    ull base0 = 0;
    if (lane == 0) base0 = ld_acq(myflag);
    const ull base = __shfl_sync(0xFFFFFFFFu, base0, 0);

    // ---- stage R transposed into smem [j][k] (once) ----
#pragma unroll
    for (int p = 0; p < 8; ++p) {
        int idx = tid + p * TPB;
        int k = idx >> 2, q = idx & 3;
        float4 v = *(const float4*)(R + (size_t)k * DH + jBase + q * 4);
        S[R_OFF + (q * 4 + 0) * HSTRIDE + k] = v.x;
        S[R_OFF + (q * 4 + 1) * HSTRIDE + k] = v.y;
        S[R_OFF + (q * 4 + 2) * HSTRIDE + k] = v.z;
        S[R_OFF + (q * 4 + 3) * HSTRIDE + k] = v.w;
    }
    __syncthreads();

    const float* Hp = S + H_OFF + (size_t)m_lane * HSTRIDE + w * 64;
    const float* Rp = S + R_OFF + (size_t)j_lane * HSTRIDE + w * 64;
    const int m_l = tid >> 4, j_l = tid & 15;       // epilogue decode

    // h staging decode: lanes 0-15 row 2p, lanes 16-31 row 2p+1
    const int kf    = w * 64 + (lane & 15) * 4;
    const int rhalf = lane >> 4;

#pragma unroll 1
    for (int t = 0; t < TSTEPS; ++t) {
        // ---- prefetch this block's preact (own tile; L1-bypass) ----
        const size_t oi = ((size_t)(mBase + m_l) * TSTEPS + t) * DH + jBase + j_l;
        const float pre = __ldcg(out + oi);

        // ---- wait for my chunk's 4 producers to finish step t-1 ----
        if (t > 0) {
            const ull target = base + 4ull * (ull)t;
            while (ld_acq(myflag) < target) { }
        }

        // ---- stage h slice via cp.async (L2 -> smem, no L1, no regs) ----
        {
            const float* hb;
            size_t rstr;
            if (t == 0) { hb = h0 + (size_t)mBase * DH; rstr = DH; }
            else {
                hb = out + (size_t)(t - 1) * DH + (size_t)mBase * ((size_t)TSTEPS * DH);
                rstr = (size_t)TSTEPS * DH;
            }
#pragma unroll
            for (int p = 0; p < 16; ++p) {
                const int row = p * 2 + rhalf;
                cp_async16(s2u(&S[H_OFF + row * HSTRIDE + kf]),
                           hb + (size_t)row * rstr + kf);
            }
            cp_async_wait_all();
        }
        __syncwarp();

        // ---- compute: 4x4 micro-tile, f32x2 pairs over k ----
        ull acc[4][4];
#pragma unroll
        for (int mi = 0; mi < 4; ++mi)
#pragma unroll
            for (int ji = 0; ji < 4; ++ji) acc[mi][ji] = 0ull;

#pragma unroll 4
        for (int it = 0; it < 16; ++it) {
            const int off = it * 4;
            float4 h[4], r[4];
#pragma unroll
            for (int mi = 0; mi < 4; ++mi)
                h[mi] = *(const float4*)(Hp + (size_t)(mi * 8) * HSTRIDE + off);
#pragma unroll
            for (int ji = 0; ji < 4; ++ji)
                r[ji] = *(const float4*)(Rp + (size_t)(ji * 4) * HSTRIDE + off);
#pragma unroll
            for (int mi = 0; mi < 4; ++mi) {
                ull hlo = f2u(make_float2(h[mi].x, h[mi].y));
                ull hhi = f2u(make_float2(h[mi].z, h[mi].w));
#pragma unroll
                for (int ji = 0; ji < 4; ++ji) {
                    fma2(acc[mi][ji], hlo, f2u(make_float2(r[ji].x, r[ji].y)));
                    fma2(acc[mi][ji], hhi, f2u(make_float2(r[ji].z, r[ji].w)));
                }
            }
        }

        // ---- partials to separate P region (no pre-sync needed) ----
#pragma unroll
        for (int mi = 0; mi < 4; ++mi)
#pragma unroll
            for (int ji = 0; ji < 4; ++ji) {
                float2 c = u2f(acc[mi][ji]);
                int m_loc = m_lane + 8 * mi;
                int j_loc = j_lane + 4 * ji;
                S[P_OFF + (m_loc * 16 + j_loc) * 17 + w] = c.x + c.y;
            }
        __syncthreads();   // (a) partials visible

        // ---- reduce 16 partials + preact + tanh + store h_t ----
        {
            const float* row = S + P_OFF + tid * 17;
            float s0 = 0.f, s1 = 0.f;
#pragma unroll
            for (int q = 0; q < 8; ++q) { s0 += row[q]; s1 += row[q + 8]; }
            out[oi] = tanhf(pre + s0 + s1);
        }

        __syncthreads();   // (b) P reads + STGs done (WAR for next Pwrite,
                           //     happens-before for the release below)

        // ---- announce: this block finished step t ----
        if (tid == 0) red_rel_add(prodflag, 1ull);
    }
}

// ---------------- launch ----------------
extern "C" void kernel_launch(void* const* d_in, const int* in_sizes, int n_in,
                              void* d_out, int out_size)
{
    const float* x  = (const float*)d_in[0];   // [64,512,512]
    const float* h0 = (const float*)d_in[1];   // [64,1024]
    const float* W  = (const float*)d_in[2];   // [512,1024]
    const float* R  = (const float*)d_in[3];   // [1024,1024]
    const float* b  = (const float*)d_in[4];   // [1,1024]
    float* out = (float*)d_out;                // [64,512,1024]

    const int smem_bytes = SMEM_FLOATS * 4;    // 232192 <= 232448 (227KB cap)
    cudaFuncSetAttribute(rnn_recur_kernel,
                         cudaFuncAttributeMaxDynamicSharedMemorySize, smem_bytes);

    dim3 gridA(DH / 128, (BATCH * TSTEPS) / 128);  // (8, 256)
    gemm_xw_kernel<<<gridA, 256>>>(x, W, b, out);

    rnn_recur_kernel<<<128, TPB, smem_bytes>>>(h0, R, out);
}